// round 1
// baseline (speedup 1.0000x reference)
#include <cuda_runtime.h>
#include <math.h>

#define NB 64
#define LOOKBACK 32
#define NS 256
#define DM 512
#define DK 128
#define DV 128
#define NSPLIT 16
#define SPER (NS / NSPLIT)   // 16 stocks per CTA in main kernel

// ---- scratch (device globals: allocation-free) ----
__device__ float  g_u[NB * DM];            // u[b,d] = (q[b] @ W_k)[d] * 1/sqrt(DK)
__device__ float4 g_stock[NS];             // per-stock: {alpha, gate, lag_floor, lag_ceil}
__device__ float  g_pctx[NB * NSPLIT * DM];// split partial contexts (unnormalized)
__device__ float  g_m[NB * NSPLIT];        // split running max
__device__ float  g_l[NB * NSPLIT];        // split running sum

__device__ __forceinline__ float sigmoidf_(float x) {
    return 1.0f / (1.0f + __expf(-x));
}

// ============================================================================
// Kernel 1: prep.
//   - per-stock lag table (block 0)
//   - q[b,:]   = query[b,:] @ W_q^T          (64 x 128)
//   - u[b,:]   = q[b,:] @ W_k * rsqrt(128)   (64 x 512)
// 16 blocks x 512 threads; each block handles 4 batches to amortize W reads.
// ============================================================================
__global__ __launch_bounds__(512) void prep_kernel(
    const float* __restrict__ query,
    const float* __restrict__ Wq,
    const float* __restrict__ Wk,
    const float* __restrict__ lags,
    const float* __restrict__ gates,
    const void*  __restrict__ mlraw)
{
    __shared__ float qs[4][DM];   // query rows
    __shared__ float qk[4][DK];   // q = query @ Wq^T

    const int tid = threadIdx.x;          // 0..511
    const int b0  = blockIdx.x * 4;

    // ---- per-stock meta (block 0 only) ----
    if (blockIdx.x == 0 && tid < NS) {
        float ml = 16.0f;
        if (mlraw != nullptr) {
            int   iv = ((const int*)mlraw)[0];
            float fv = ((const float*)mlraw)[0];
            ml = (iv > 0 && iv <= 65536) ? (float)iv : fv;
        }
        float lag = sigmoidf_(lags[tid]) * ml;
        float fl  = floorf(lag);
        float cl  = ceilf(lag);
        int ifl = min(max((int)fl, 0), LOOKBACK - 1);
        int icl = min(max((int)cl, 0), LOOKBACK - 1);
        float alpha = lag - (float)ifl;
        float gate  = sigmoidf_(gates[tid]);
        g_stock[tid] = make_float4(alpha, gate, (float)ifl, (float)icl);
    }

    // ---- load 4 query rows into smem ----
    for (int i = tid; i < 4 * DM; i += 512)
        qs[i >> 9][i & 511] = query[(size_t)(b0 + (i >> 9)) * DM + (i & 511)];
    __syncthreads();

    // ---- stage A: q[b,k] = sum_d query[b,d] * Wq[k,d] ----
    // one warp per k; 16 warps -> 8 rounds; coalesced Wq reads.
    const int wid  = tid >> 5;
    const int lane = tid & 31;
    for (int j = 0; j < 8; j++) {
        int k = wid + j * 16;
        float a0 = 0.f, a1 = 0.f, a2 = 0.f, a3 = 0.f;
        #pragma unroll
        for (int i = 0; i < 16; i++) {
            float w = Wq[(size_t)k * DM + i * 32 + lane];
            float q0 = qs[0][i * 32 + lane];
            float q1 = qs[1][i * 32 + lane];
            float q2 = qs[2][i * 32 + lane];
            float q3 = qs[3][i * 32 + lane];
            a0 = fmaf(w, q0, a0);
            a1 = fmaf(w, q1, a1);
            a2 = fmaf(w, q2, a2);
            a3 = fmaf(w, q3, a3);
        }
        #pragma unroll
        for (int off = 16; off; off >>= 1) {
            a0 += __shfl_xor_sync(0xffffffffu, a0, off);
            a1 += __shfl_xor_sync(0xffffffffu, a1, off);
            a2 += __shfl_xor_sync(0xffffffffu, a2, off);
            a3 += __shfl_xor_sync(0xffffffffu, a3, off);
        }
        if (lane == 0) {
            qk[0][k] = a0; qk[1][k] = a1; qk[2][k] = a2; qk[3][k] = a3;
        }
    }
    __syncthreads();

    // ---- stage B: u[b,d] = sum_k q[b,k] * Wk[k,d], scaled by 1/sqrt(DK) ----
    // thread t = column d; coalesced Wk reads.
    const float inv = 0.08838834764831845f;  // 1/sqrt(128)
    float a0 = 0.f, a1 = 0.f, a2 = 0.f, a3 = 0.f;
    #pragma unroll 4
    for (int k = 0; k < DK; k++) {
        float w = Wk[(size_t)k * DM + tid];
        a0 = fmaf(qk[0][k], w, a0);
        a1 = fmaf(qk[1][k], w, a1);
        a2 = fmaf(qk[2][k], w, a2);
        a3 = fmaf(qk[3][k], w, a3);
    }
    g_u[(size_t)(b0 + 0) * DM + tid] = a0 * inv;
    g_u[(size_t)(b0 + 1) * DM + tid] = a1 * inv;
    g_u[(size_t)(b0 + 2) * DM + tid] = a2 * inv;
    g_u[(size_t)(b0 + 3) * DM + tid] = a3 * inv;
}

// ============================================================================
// Kernel 2: main. Split-softmax over stocks.
// grid = (NSPLIT, NB), 128 threads. Each thread owns 4 dims (float4).
// Per stock: load floor+ceil rows (LDG.128, coalesced), interpolate,
// block-reduce dot with u, online-softmax update of a 4-dim ctx slice.
// Next stock's loads are software-prefetched before the reduction barrier.
// ============================================================================
__global__ __launch_bounds__(128) void main_kernel(const float* __restrict__ embs)
{
    const int tid = threadIdx.x;    // 0..127
    const int b   = blockIdx.y;
    const int sp  = blockIdx.x;
    const int s0  = sp * SPER;

    const float4* base = (const float4*)embs + (size_t)b * LOOKBACK * NS * (DM / 4);
    const float4  u4   = ((const float4*)g_u)[(size_t)b * (DM / 4) + tid];

    __shared__ float ws[4];

    float  m   = -INFINITY;
    float  l   = 0.f;
    float4 ctx = make_float4(0.f, 0.f, 0.f, 0.f);

    // prefetch stock s0
    float4 meta = g_stock[s0];
    float4 f = base[((int)meta.z * NS + s0) * (DM / 4) + tid];
    float4 c = base[((int)meta.w * NS + s0) * (DM / 4) + tid];
    float  a = meta.x, g = meta.y;

    #pragma unroll
    for (int i = 0; i < SPER; i++) {
        float4 fn = make_float4(0.f, 0.f, 0.f, 0.f);
        float4 cn = fn;
        float  an = 0.f, gn = 0.f;
        if (i + 1 < SPER) {
            int s = s0 + i + 1;
            float4 mt = g_stock[s];
            fn = base[((int)mt.z * NS + s) * (DM / 4) + tid];
            cn = base[((int)mt.w * NS + s) * (DM / 4) + tid];
            an = mt.x; gn = mt.y;
        }

        // interpolate exactly as reference: (1-a)*floor + a*ceil
        float oma = 1.0f - a;
        float4 e;
        e.x = oma * f.x + a * c.x;
        e.y = oma * f.y + a * c.y;
        e.z = oma * f.z + a * c.z;
        e.w = oma * f.w + a * c.w;

        float part = e.x * u4.x + e.y * u4.y + e.z * u4.z + e.w * u4.w;
        #pragma unroll
        for (int off = 16; off; off >>= 1)
            part += __shfl_xor_sync(0xffffffffu, part, off);
        if ((tid & 31) == 0) ws[tid >> 5] = part;
        __syncthreads();
        float score = (ws[0] + ws[1] + ws[2] + ws[3]) * g;  // 1/sqrt(dk) folded into u
        __syncthreads();

        // online softmax
        float mnew = fmaxf(m, score);
        float corr = __expf(m - mnew);     // first iter: exp(-inf)=0
        float p    = __expf(score - mnew);
        l = l * corr + p;
        ctx.x = ctx.x * corr + p * e.x;
        ctx.y = ctx.y * corr + p * e.y;
        ctx.z = ctx.z * corr + p * e.z;
        ctx.w = ctx.w * corr + p * e.w;
        m = mnew;

        f = fn; c = cn; a = an; g = gn;
    }

    const int idx = b * NSPLIT + sp;
    if (tid == 0) { g_m[idx] = m; g_l[idx] = l; }
    ((float4*)g_pctx)[(size_t)idx * (DM / 4) + tid] = ctx;
}

// ============================================================================
// Kernel 3: combine split partials + apply W_v.
// 16 blocks x 512 threads; each block handles 4 batches.
// ============================================================================
__global__ __launch_bounds__(512) void finish_kernel(
    const float* __restrict__ Wv,
    float*       __restrict__ out)
{
    __shared__ float4 ctxs[4][DM / 4];
    __shared__ float  wsm[4][NSPLIT];

    const int tid = threadIdx.x;     // 0..511
    const int b0  = blockIdx.x * 4;

    // per-batch split combine weights (serial, trivial)
    if (tid < 4) {
        int b = b0 + tid;
        float mg = -INFINITY;
        #pragma unroll
        for (int i = 0; i < NSPLIT; i++) mg = fmaxf(mg, g_m[b * NSPLIT + i]);
        float tmp[NSPLIT];
        float L = 0.f;
        #pragma unroll
        for (int i = 0; i < NSPLIT; i++) {
            float w = __expf(g_m[b * NSPLIT + i] - mg);
            tmp[i] = w;
            L += w * g_l[b * NSPLIT + i];
        }
        float invL = 1.0f / L;
        #pragma unroll
        for (int i = 0; i < NSPLIT; i++) wsm[tid][i] = tmp[i] * invL;
    }
    __syncthreads();

    // ctx_emb[b,d] = sum_split w * pctx[b,split,d]
    const int bl = tid >> 7;      // batch-local 0..3
    const int j  = tid & 127;     // float4 column 0..127
    float4 acc = make_float4(0.f, 0.f, 0.f, 0.f);
    const float4* pc = (const float4*)g_pctx
                     + (size_t)(b0 + bl) * NSPLIT * (DM / 4) + j;
    #pragma unroll
    for (int spp = 0; spp < NSPLIT; spp++) {
        float4 v = pc[(size_t)spp * (DM / 4)];
        float  w = wsm[bl][spp];
        acc.x += w * v.x; acc.y += w * v.y;
        acc.z += w * v.z; acc.w += w * v.w;
    }
    ctxs[bl][j] = acc;
    __syncthreads();

    // context[b,v] = sum_d ctx_emb[b,d] * Wv[v,d]
    const int v = j;   // 0..127 output dim
    float s = 0.f;
    const float4* wv = (const float4*)Wv + (size_t)v * (DM / 4);
    #pragma unroll 8
    for (int d = 0; d < DM / 4; d++) {
        float4 w4 = wv[d];
        float4 cx = ctxs[bl][d];
        s += w4.x * cx.x + w4.y * cx.y + w4.z * cx.z + w4.w * cx.w;
    }
    out[(size_t)(b0 + bl) * DV + v] = s;
}

// ============================================================================
extern "C" void kernel_launch(void* const* d_in, const int* in_sizes, int n_in,
                              void* d_out, int out_size)
{
    const float* query = (const float*)d_in[0];   // [64, 512]
    const float* embs  = (const float*)d_in[1];   // [64, 32, 256, 512]
    const float* Wq    = (const float*)d_in[2];   // [128, 512]
    const float* Wk    = (const float*)d_in[3];   // [128, 512]
    const float* Wv    = (const float*)d_in[4];   // [128, 512]
    const float* lags  = (const float*)d_in[5];   // [256]
    const float* gates = (const float*)d_in[6];   // [256]
    const void*  ml    = (n_in > 7) ? d_in[7] : nullptr;

    prep_kernel<<<16, 512>>>(query, Wq, Wk, lags, gates, ml);
    main_kernel<<<dim3(NSPLIT, NB), 128>>>(embs);
    finish_kernel<<<16, 512>>>(Wv, (float*)d_out);
}

// round 2
// speedup vs baseline: 1.1536x; 1.1536x over previous
#include <cuda_runtime.h>
#include <math.h>

#define NB 64
#define LOOKBACK 32
#define NS 256
#define DM 512
#define DK 128
#define DV 128
#define WST 8                  // stocks per warp in main kernel
#define CPB (NS / (4 * WST))   // CTAs per batch in main = 8
#define NPART (CPB * 4)        // 32 warp-partials per batch

// ---- scratch (device globals: allocation-free) ----
__device__ float  g_u[NB * DM];             // u[b,d] = (q[b] @ W_k)[d] / sqrt(DK)
__device__ float4 g_stock[NS];              // {alpha, gate, lag_floor, lag_ceil}
__device__ float  g_pctx[NB * NPART * DM];  // warp partial contexts (unnormalized)
__device__ float  g_m[NB * NPART];          // warp running max
__device__ float  g_l[NB * NPART];          // warp running sum

__device__ __forceinline__ float sigmoidf_(float x) {
    return 1.0f / (1.0f + __expf(-x));
}

// ============================================================================
// Kernel 1: prep. One CTA per batch (64 CTAs x 512 threads).
//   q[b,:] = query[b,:] @ W_q^T   (stage A: warp-per-k, coalesced)
//   u[b,:] = q[b,:] @ W_k / sqrt(128)  (stage B: thread-per-d, coalesced)
// ============================================================================
__global__ __launch_bounds__(512) void prep_kernel(
    const float* __restrict__ query,
    const float* __restrict__ Wq,
    const float* __restrict__ Wk,
    const float* __restrict__ lags,
    const float* __restrict__ gates,
    const void*  __restrict__ mlraw)
{
    __shared__ float qs[DM];
    __shared__ float qk[DK];

    const int tid = threadIdx.x;    // 0..511
    const int b   = blockIdx.x;

    // per-stock meta (block 0 only)
    if (b == 0 && tid < NS) {
        float ml = 16.0f;
        if (mlraw != nullptr) {
            int   iv = ((const int*)mlraw)[0];
            float fv = ((const float*)mlraw)[0];
            ml = (iv > 0 && iv <= 65536) ? (float)iv : fv;
        }
        float lag = sigmoidf_(lags[tid]) * ml;
        int ifl = min(max((int)floorf(lag), 0), LOOKBACK - 1);
        int icl = min(max((int)ceilf(lag),  0), LOOKBACK - 1);
        float alpha = lag - (float)ifl;
        float gate  = sigmoidf_(gates[tid]);
        g_stock[tid] = make_float4(alpha, gate, (float)ifl, (float)icl);
    }

    qs[tid] = query[(size_t)b * DM + tid];
    __syncthreads();

    // ---- stage A: q[b,k] = sum_d query[b,d] * Wq[k,d] ----
    const int wid  = tid >> 5;
    const int lane = tid & 31;
    #pragma unroll
    for (int j = 0; j < 8; j++) {
        const int k = j * 16 + wid;
        float acc = 0.f;
        #pragma unroll
        for (int i = 0; i < 16; i++)
            acc = fmaf(Wq[(size_t)k * DM + i * 32 + lane], qs[i * 32 + lane], acc);
        #pragma unroll
        for (int off = 16; off; off >>= 1)
            acc += __shfl_xor_sync(0xffffffffu, acc, off);
        if (lane == 0) qk[k] = acc;
    }
    __syncthreads();

    // ---- stage B: u[b,d] = sum_k q[b,k] * Wk[k,d] ----
    float a0 = 0.f, a1 = 0.f, a2 = 0.f, a3 = 0.f;
    #pragma unroll 8
    for (int k = 0; k < DK; k += 4) {
        a0 = fmaf(qk[k + 0], Wk[(size_t)(k + 0) * DM + tid], a0);
        a1 = fmaf(qk[k + 1], Wk[(size_t)(k + 1) * DM + tid], a1);
        a2 = fmaf(qk[k + 2], Wk[(size_t)(k + 2) * DM + tid], a2);
        a3 = fmaf(qk[k + 3], Wk[(size_t)(k + 3) * DM + tid], a3);
    }
    const float inv = 0.08838834764831845f;  // 1/sqrt(128)
    g_u[(size_t)b * DM + tid] = ((a0 + a1) + (a2 + a3)) * inv;
}

// ============================================================================
// Kernel 2: main. Warp-autonomous split online-softmax — no barriers in loop.
// grid = (CPB, NB), 128 threads. Each warp handles WST=8 stocks; a lane holds
// 4 float4 slices (dims interleaved by 128-float4 stride).
// ============================================================================
__global__ __launch_bounds__(128) void main_kernel(const float* __restrict__ embs)
{
    const int tid  = threadIdx.x;
    const int lane = tid & 31;
    const int wid  = tid >> 5;
    const int b    = blockIdx.y;
    const int s0   = (blockIdx.x * 4 + wid) * WST;

    const float4* base = (const float4*)embs + (size_t)b * LOOKBACK * NS * (DM / 4);
    const float4* ub   = (const float4*)g_u  + (size_t)b * (DM / 4);

    const float4 u0 = ub[lane], u1 = ub[32 + lane], u2 = ub[64 + lane], u3 = ub[96 + lane];

    float  m = -INFINITY, l = 0.f;
    float4 x0 = make_float4(0.f,0.f,0.f,0.f), x1 = x0, x2 = x0, x3 = x0;

    // prefetch stock s0
    float4 meta = g_stock[s0];
    const float4* rf = base + ((int)meta.z * NS + s0) * (DM / 4);
    const float4* rc = base + ((int)meta.w * NS + s0) * (DM / 4);
    float4 f0 = rf[lane], f1 = rf[32+lane], f2 = rf[64+lane], f3 = rf[96+lane];
    float4 c0 = rc[lane], c1 = rc[32+lane], c2 = rc[64+lane], c3 = rc[96+lane];
    float  a  = meta.x, gt = meta.y;

    #pragma unroll
    for (int i = 0; i < WST; i++) {
        float4 nf0, nf1, nf2, nf3, nc0, nc1, nc2, nc3;
        float  na = 0.f, ngt = 0.f;
        if (i + 1 < WST) {
            const int s = s0 + i + 1;
            float4 mt = g_stock[s];
            const float4* prf = base + ((int)mt.z * NS + s) * (DM / 4);
            const float4* prc = base + ((int)mt.w * NS + s) * (DM / 4);
            nf0 = prf[lane]; nf1 = prf[32+lane]; nf2 = prf[64+lane]; nf3 = prf[96+lane];
            nc0 = prc[lane]; nc1 = prc[32+lane]; nc2 = prc[64+lane]; nc3 = prc[96+lane];
            na = mt.x; ngt = mt.y;
        }

        // interpolate in-place: f <- (1-a)*f + a*c  (reference order)
        const float oma = 1.0f - a;
        f0.x = oma*f0.x + a*c0.x; f0.y = oma*f0.y + a*c0.y; f0.z = oma*f0.z + a*c0.z; f0.w = oma*f0.w + a*c0.w;
        f1.x = oma*f1.x + a*c1.x; f1.y = oma*f1.y + a*c1.y; f1.z = oma*f1.z + a*c1.z; f1.w = oma*f1.w + a*c1.w;
        f2.x = oma*f2.x + a*c2.x; f2.y = oma*f2.y + a*c2.y; f2.z = oma*f2.z + a*c2.z; f2.w = oma*f2.w + a*c2.w;
        f3.x = oma*f3.x + a*c3.x; f3.y = oma*f3.y + a*c3.y; f3.z = oma*f3.z + a*c3.z; f3.w = oma*f3.w + a*c3.w;

        // dot(e, u) with warp reduce (no smem, no barrier)
        float part = f0.x*u0.x + f0.y*u0.y + f0.z*u0.z + f0.w*u0.w
                   + f1.x*u1.x + f1.y*u1.y + f1.z*u1.z + f1.w*u1.w
                   + f2.x*u2.x + f2.y*u2.y + f2.z*u2.z + f2.w*u2.w
                   + f3.x*u3.x + f3.y*u3.y + f3.z*u3.z + f3.w*u3.w;
        #pragma unroll
        for (int off = 16; off; off >>= 1)
            part += __shfl_xor_sync(0xffffffffu, part, off);
        const float score = part * gt;   // 1/sqrt(dk) folded into u

        // online softmax update
        const float mnew = fmaxf(m, score);
        const float corr = __expf(m - mnew);
        const float p    = __expf(score - mnew);
        l = l * corr + p;
        x0.x = x0.x*corr + p*f0.x; x0.y = x0.y*corr + p*f0.y; x0.z = x0.z*corr + p*f0.z; x0.w = x0.w*corr + p*f0.w;
        x1.x = x1.x*corr + p*f1.x; x1.y = x1.y*corr + p*f1.y; x1.z = x1.z*corr + p*f1.z; x1.w = x1.w*corr + p*f1.w;
        x2.x = x2.x*corr + p*f2.x; x2.y = x2.y*corr + p*f2.y; x2.z = x2.z*corr + p*f2.z; x2.w = x2.w*corr + p*f2.w;
        x3.x = x3.x*corr + p*f3.x; x3.y = x3.y*corr + p*f3.y; x3.z = x3.z*corr + p*f3.z; x3.w = x3.w*corr + p*f3.w;
        m = mnew;

        f0 = nf0; f1 = nf1; f2 = nf2; f3 = nf3;
        c0 = nc0; c1 = nc1; c2 = nc2; c3 = nc3;
        a  = na;  gt = ngt;
    }

    const int idx = (b * CPB + blockIdx.x) * 4 + wid;
    if (lane == 0) { g_m[idx] = m; g_l[idx] = l; }
    float4* pc = (float4*)g_pctx + (size_t)idx * (DM / 4);
    pc[lane] = x0; pc[32 + lane] = x1; pc[64 + lane] = x2; pc[96 + lane] = x3;
}

// ============================================================================
// Kernel 3: combine 32 warp-partials per batch + apply W_v.
// 16 blocks x 512 threads; 4 batches per block.
// ============================================================================
__global__ __launch_bounds__(512) void finish_kernel(
    const float* __restrict__ Wv,
    float*       __restrict__ out)
{
    __shared__ float4 ctxs[4][DM / 4];
    __shared__ float  wsm[4][NPART];

    const int tid = threadIdx.x;
    const int b0  = blockIdx.x * 4;

    if (tid < 4) {
        const int b = b0 + tid;
        float mg = -INFINITY;
        #pragma unroll
        for (int i = 0; i < NPART; i++) mg = fmaxf(mg, g_m[b * NPART + i]);
        float L = 0.f;
        float tmp[NPART];
        #pragma unroll
        for (int i = 0; i < NPART; i++) {
            float w = __expf(g_m[b * NPART + i] - mg);
            tmp[i] = w;
            L += w * g_l[b * NPART + i];
        }
        const float invL = 1.0f / L;
        #pragma unroll
        for (int i = 0; i < NPART; i++) wsm[tid][i] = tmp[i] * invL;
    }
    __syncthreads();

    const int bl = tid >> 7;   // 0..3 batch-local
    const int j  = tid & 127;  // float4 column
    float4 acc = make_float4(0.f, 0.f, 0.f, 0.f);
    const float4* pc = (const float4*)g_pctx
                     + (size_t)(b0 + bl) * NPART * (DM / 4) + j;
    #pragma unroll
    for (int sp = 0; sp < NPART; sp++) {
        const float4 v = pc[(size_t)sp * (DM / 4)];
        const float  w = wsm[bl][sp];
        acc.x += w * v.x; acc.y += w * v.y; acc.z += w * v.z; acc.w += w * v.w;
    }
    ctxs[bl][j] = acc;
    __syncthreads();

    // context[b,v] = sum_d ctx_emb[b,d] * Wv[v,d]
    float s = 0.f;
    const float4* wv = (const float4*)Wv + (size_t)j * (DM / 4);
    #pragma unroll 8
    for (int d = 0; d < DM / 4; d++) {
        const float4 w4 = wv[d];
        const float4 cx = ctxs[bl][d];
        s += w4.x * cx.x + w4.y * cx.y + w4.z * cx.z + w4.w * cx.w;
    }
    out[(size_t)(b0 + bl) * DV + j] = s;
}

// ============================================================================
extern "C" void kernel_launch(void* const* d_in, const int* in_sizes, int n_in,
                              void* d_out, int out_size)
{
    const float* query = (const float*)d_in[0];   // [64, 512]
    const float* embs  = (const float*)d_in[1];   // [64, 32, 256, 512]
    const float* Wq    = (const float*)d_in[2];   // [128, 512]
    const float* Wk    = (const float*)d_in[3];   // [128, 512]
    const float* Wv    = (const float*)d_in[4];   // [128, 512]
    const float* lags  = (const float*)d_in[5];   // [256]
    const float* gates = (const float*)d_in[6];   // [256]
    const void*  ml    = (n_in > 7) ? d_in[7] : nullptr;

    prep_kernel<<<NB, 512>>>(query, Wq, Wk, lags, gates, ml);
    main_kernel<<<dim3(CPB, NB), 128>>>(embs);
    finish_kernel<<<16, 512>>>(Wv, (float*)d_out);
}

// round 3
// speedup vs baseline: 1.3102x; 1.1358x over previous
#include <cuda_runtime.h>
#include <math.h>

#define NB 64
#define LOOKBACK 32
#define NS 256
#define DM 512
#define DK 128
#define DV 128
#define WST 8                  // stocks per warp in main kernel
#define CPB (NS / (4 * WST))   // CTAs per batch in main = 8
#define NPART CPB              // 8 CTA-partials per batch

// ---- scratch (device globals: allocation-free) ----
__device__ float  g_u[NB * DM];             // u[b,d] = (q[b] @ W_k)[d] / sqrt(DK)
__device__ float4 g_stock[NS];              // {alpha, gate, lag_floor, lag_ceil}
__device__ float  g_pctx[NB * NPART * DM];  // CTA partial contexts (unnormalized)
__device__ float  g_m[NB * NPART];          // CTA running max
__device__ float  g_l[NB * NPART];          // CTA running sum

__device__ __forceinline__ float sigmoidf_(float x) {
    return 1.0f / (1.0f + __expf(-x));
}

// ============================================================================
// Kernel 1: prep. One CTA per batch (64 CTAs x 512 threads).
// ============================================================================
__global__ __launch_bounds__(512) void prep_kernel(
    const float* __restrict__ query,
    const float* __restrict__ Wq,
    const float* __restrict__ Wk,
    const float* __restrict__ lags,
    const float* __restrict__ gates,
    const void*  __restrict__ mlraw)
{
    __shared__ float  qs[DM];
    __shared__ float  qk[DK];
    __shared__ float4 sred[4][DM / 4];   // stage-B partial sums, 8 KB

    const int tid = threadIdx.x;    // 0..511
    const int b   = blockIdx.x;

    // per-stock meta (block 0 only)
    if (b == 0 && tid < NS) {
        float ml = 16.0f;
        if (mlraw != nullptr) {
            int   iv = ((const int*)mlraw)[0];
            float fv = ((const float*)mlraw)[0];
            ml = (iv > 0 && iv <= 65536) ? (float)iv : fv;
        }
        float lag = sigmoidf_(lags[tid]) * ml;
        int ifl = min(max((int)floorf(lag), 0), LOOKBACK - 1);
        int icl = min(max((int)ceilf(lag),  0), LOOKBACK - 1);
        float alpha = lag - (float)ifl;
        float gate  = sigmoidf_(gates[tid]);
        g_stock[tid] = make_float4(alpha, gate, (float)ifl, (float)icl);
    }

    qs[tid] = query[(size_t)b * DM + tid];
    __syncthreads();

    // ---- stage A: q[b,k] = sum_d query[b,d] * Wq[k,d] ----
    // 16 warps; warp handles k = j*16 + wid for j=0..7. Coalesced scalar loads,
    // all 16 loads per k independent (high MLP).
    const int wid  = tid >> 5;
    const int lane = tid & 31;
    #pragma unroll
    for (int j = 0; j < 8; j++) {
        const int k = j * 16 + wid;
        float acc = 0.f;
        #pragma unroll
        for (int i = 0; i < 16; i++)
            acc = fmaf(Wq[(size_t)k * DM + i * 32 + lane], qs[i * 32 + lane], acc);
        #pragma unroll
        for (int off = 16; off; off >>= 1)
            acc += __shfl_xor_sync(0xffffffffu, acc, off);
        if (lane == 0) qk[k] = acc;
    }
    __syncthreads();

    // ---- stage B: u[b,d] = sum_k q[b,k] * Wk[k,d], K split 4 ways ----
    // thread = (g, t): g = k-group (0..3), t = float4 column (0..127).
    const int g = tid >> 7;        // 0..3
    const int t = tid & 127;       // 0..127
    float4 acc0 = make_float4(0.f, 0.f, 0.f, 0.f);
    float4 acc1 = acc0;
    const float4* wkb = (const float4*)Wk + (size_t)(g * 32) * (DM / 4) + t;
    #pragma unroll 8
    for (int k = 0; k < 32; k += 2) {
        const float  s0 = qk[g * 32 + k];
        const float  s1 = qk[g * 32 + k + 1];
        const float4 w0 = wkb[(size_t)k * (DM / 4)];
        const float4 w1 = wkb[(size_t)(k + 1) * (DM / 4)];
        acc0.x = fmaf(s0, w0.x, acc0.x); acc0.y = fmaf(s0, w0.y, acc0.y);
        acc0.z = fmaf(s0, w0.z, acc0.z); acc0.w = fmaf(s0, w0.w, acc0.w);
        acc1.x = fmaf(s1, w1.x, acc1.x); acc1.y = fmaf(s1, w1.y, acc1.y);
        acc1.z = fmaf(s1, w1.z, acc1.z); acc1.w = fmaf(s1, w1.w, acc1.w);
    }
    acc0.x += acc1.x; acc0.y += acc1.y; acc0.z += acc1.z; acc0.w += acc1.w;
    sred[g][t] = acc0;
    __syncthreads();

    if (tid < 128) {
        const float inv = 0.08838834764831845f;  // 1/sqrt(128)
        float4 s0 = sred[0][tid], s1 = sred[1][tid], s2 = sred[2][tid], s3 = sred[3][tid];
        float4 r;
        r.x = ((s0.x + s1.x) + (s2.x + s3.x)) * inv;
        r.y = ((s0.y + s1.y) + (s2.y + s3.y)) * inv;
        r.z = ((s0.z + s1.z) + (s2.z + s3.z)) * inv;
        r.w = ((s0.w + s1.w) + (s2.w + s3.w)) * inv;
        ((float4*)g_u)[(size_t)b * (DM / 4) + tid] = r;
    }
}

// ============================================================================
// Kernel 2: main. Warp-autonomous online softmax, u in smem, 1-deep prefetch,
// CTA-level combine of the 4 warp partials.
// grid = (CPB, NB), 128 threads.
// ============================================================================
__global__ __launch_bounds__(128) void main_kernel(const float* __restrict__ embs)
{
    __shared__ float4 us[DM / 4];          // 2 KB: u row (shared by all warps)
    __shared__ float4 sctx[4][DM / 4];     // 8 KB: per-warp ctx for combine
    __shared__ float  sml[4][2];           // per-warp (m, l)

    const int tid  = threadIdx.x;
    const int lane = tid & 31;
    const int wid  = tid >> 5;
    const int b    = blockIdx.y;
    const int s0   = (blockIdx.x * 4 + wid) * WST;

    const float4* base = (const float4*)embs + (size_t)b * LOOKBACK * NS * (DM / 4);

    us[tid] = ((const float4*)g_u)[(size_t)b * (DM / 4) + tid];
    __syncthreads();

    float  m = -INFINITY, l = 0.f;
    float4 x0 = make_float4(0.f,0.f,0.f,0.f), x1 = x0, x2 = x0, x3 = x0;

    // prefetch stock s0
    float4 meta = g_stock[s0];
    {
    }
    const float4* rf0 = base + ((int)meta.z * NS + s0) * (DM / 4);
    const float4* rc0 = base + ((int)meta.w * NS + s0) * (DM / 4);
    float4 f0 = rf0[lane], f1 = rf0[32+lane], f2 = rf0[64+lane], f3 = rf0[96+lane];
    float4 c0 = rc0[lane], c1 = rc0[32+lane], c2 = rc0[64+lane], c3 = rc0[96+lane];
    float  a  = meta.x, gt = meta.y;

    #pragma unroll
    for (int i = 0; i < WST; i++) {
        float4 nf0, nf1, nf2, nf3, nc0, nc1, nc2, nc3;
        float  na = 0.f, ngt = 0.f;
        if (i + 1 < WST) {
            const int s = s0 + i + 1;
            const float4 mt = g_stock[s];
            const float4* prf = base + ((int)mt.z * NS + s) * (DM / 4);
            const float4* prc = base + ((int)mt.w * NS + s) * (DM / 4);
            nf0 = prf[lane]; nf1 = prf[32+lane]; nf2 = prf[64+lane]; nf3 = prf[96+lane];
            nc0 = prc[lane]; nc1 = prc[32+lane]; nc2 = prc[64+lane]; nc3 = prc[96+lane];
            na = mt.x; ngt = mt.y;
        }

        // interpolate, consuming c immediately: e = (1-a)*f + a*c
        const float oma = 1.0f - a;
        f0.x = oma*f0.x + a*c0.x; f0.y = oma*f0.y + a*c0.y; f0.z = oma*f0.z + a*c0.z; f0.w = oma*f0.w + a*c0.w;
        f1.x = oma*f1.x + a*c1.x; f1.y = oma*f1.y + a*c1.y; f1.z = oma*f1.z + a*c1.z; f1.w = oma*f1.w + a*c1.w;
        f2.x = oma*f2.x + a*c2.x; f2.y = oma*f2.y + a*c2.y; f2.z = oma*f2.z + a*c2.z; f2.w = oma*f2.w + a*c2.w;
        f3.x = oma*f3.x + a*c3.x; f3.y = oma*f3.y + a*c3.y; f3.z = oma*f3.z + a*c3.z; f3.w = oma*f3.w + a*c3.w;

        // dot(e, u) — u from smem (broadcast-free strided, conflict-free)
        const float4 u0 = us[lane], u1 = us[32+lane], u2 = us[64+lane], u3 = us[96+lane];
        float p0 = f0.x*u0.x + f0.y*u0.y + f0.z*u0.z + f0.w*u0.w;
        float p1 = f1.x*u1.x + f1.y*u1.y + f1.z*u1.z + f1.w*u1.w;
        float p2 = f2.x*u2.x + f2.y*u2.y + f2.z*u2.z + f2.w*u2.w;
        float p3 = f3.x*u3.x + f3.y*u3.y + f3.z*u3.z + f3.w*u3.w;
        float part = (p0 + p1) + (p2 + p3);
        #pragma unroll
        for (int off = 16; off; off >>= 1)
            part += __shfl_xor_sync(0xffffffffu, part, off);
        const float score = part * gt;   // 1/sqrt(dk) folded into u

        // online softmax update
        const float mnew = fmaxf(m, score);
        const float corr = __expf(m - mnew);
        const float p    = __expf(score - mnew);
        l = l * corr + p;
        x0.x = x0.x*corr + p*f0.x; x0.y = x0.y*corr + p*f0.y; x0.z = x0.z*corr + p*f0.z; x0.w = x0.w*corr + p*f0.w;
        x1.x = x1.x*corr + p*f1.x; x1.y = x1.y*corr + p*f1.y; x1.z = x1.z*corr + p*f1.z; x1.w = x1.w*corr + p*f1.w;
        x2.x = x2.x*corr + p*f2.x; x2.y = x2.y*corr + p*f2.y; x2.z = x2.z*corr + p*f2.z; x2.w = x2.w*corr + p*f2.w;
        x3.x = x3.x*corr + p*f3.x; x3.y = x3.y*corr + p*f3.y; x3.z = x3.z*corr + p*f3.z; x3.w = x3.w*corr + p*f3.w;
        m = mnew;

        f0 = nf0; f1 = nf1; f2 = nf2; f3 = nf3;
        c0 = nc0; c1 = nc1; c2 = nc2; c3 = nc3;
        a  = na;  gt = ngt;
    }

    // ---- CTA combine of 4 warp partials ----
    if (lane == 0) { sml[wid][0] = m; sml[wid][1] = l; }
    sctx[wid][lane]      = x0;
    sctx[wid][32 + lane] = x1;
    sctx[wid][64 + lane] = x2;
    sctx[wid][96 + lane] = x3;
    __syncthreads();

    // 128 threads: thread = float4 column j
    const float m0 = sml[0][0], m1 = sml[1][0], m2 = sml[2][0], m3 = sml[3][0];
    const float mg = fmaxf(fmaxf(m0, m1), fmaxf(m2, m3));
    const float w0 = __expf(m0 - mg), w1 = __expf(m1 - mg);
    const float w2 = __expf(m2 - mg), w3 = __expf(m3 - mg);

    const int idx = b * CPB + blockIdx.x;
    if (tid == 0) {
        g_m[idx] = mg;
        g_l[idx] = w0 * sml[0][1] + w1 * sml[1][1] + w2 * sml[2][1] + w3 * sml[3][1];
    }
    const float4 a0 = sctx[0][tid], a1 = sctx[1][tid], a2 = sctx[2][tid], a3 = sctx[3][tid];
    float4 comb;
    comb.x = w0*a0.x + w1*a1.x + w2*a2.x + w3*a3.x;
    comb.y = w0*a0.y + w1*a1.y + w2*a2.y + w3*a3.y;
    comb.z = w0*a0.z + w1*a1.z + w2*a2.z + w3*a3.z;
    comb.w = w0*a0.w + w1*a1.w + w2*a2.w + w3*a3.w;
    ((float4*)g_pctx)[(size_t)idx * (DM / 4) + tid] = comb;
}

// ============================================================================
// Kernel 3: combine 8 CTA-partials per batch + apply W_v.
// 16 blocks x 512 threads; 4 batches per block.
// ============================================================================
__global__ __launch_bounds__(512) void finish_kernel(
    const float* __restrict__ Wv,
    float*       __restrict__ out)
{
    __shared__ float4 ctxs[4][DM / 4];
    __shared__ float  wsm[4][NPART];

    const int tid = threadIdx.x;
    const int b0  = blockIdx.x * 4;

    if (tid < 4) {
        const int b = b0 + tid;
        float mg = -INFINITY;
        #pragma unroll
        for (int i = 0; i < NPART; i++) mg = fmaxf(mg, g_m[b * NPART + i]);
        float L = 0.f;
        float tmp[NPART];
        #pragma unroll
        for (int i = 0; i < NPART; i++) {
            float w = __expf(g_m[b * NPART + i] - mg);
            tmp[i] = w;
            L += w * g_l[b * NPART + i];
        }
        const float invL = 1.0f / L;
        #pragma unroll
        for (int i = 0; i < NPART; i++) wsm[tid][i] = tmp[i] * invL;
    }
    __syncthreads();

    const int bl = tid >> 7;   // 0..3 batch-local
    const int j  = tid & 127;  // float4 column
    float4 acc = make_float4(0.f, 0.f, 0.f, 0.f);
    const float4* pc = (const float4*)g_pctx
                     + (size_t)(b0 + bl) * NPART * (DM / 4) + j;
    #pragma unroll
    for (int sp = 0; sp < NPART; sp++) {
        const float4 v = pc[(size_t)sp * (DM / 4)];
        const float  w = wsm[bl][sp];
        acc.x += w * v.x; acc.y += w * v.y; acc.z += w * v.z; acc.w += w * v.w;
    }
    ctxs[bl][j] = acc;
    __syncthreads();

    // context[b,v] = sum_d ctx_emb[b,d] * Wv[v,d]
    float s = 0.f;
    const float4* wv = (const float4*)Wv + (size_t)j * (DM / 4);
    #pragma unroll 8
    for (int d = 0; d < DM / 4; d++) {
        const float4 w4 = wv[d];
        const float4 cx = ctxs[bl][d];
        s += w4.x * cx.x + w4.y * cx.y + w4.z * cx.z + w4.w * cx.w;
    }
    out[(size_t)(b0 + bl) * DV + j] = s;
}

// ============================================================================
extern "C" void kernel_launch(void* const* d_in, const int* in_sizes, int n_in,
                              void* d_out, int out_size)
{
    const float* query = (const float*)d_in[0];   // [64, 512]
    const float* embs  = (const float*)d_in[1];   // [64, 32, 256, 512]
    const float* Wq    = (const float*)d_in[2];   // [128, 512]
    const float* Wk    = (const float*)d_in[3];   // [128, 512]
    const float* Wv    = (const float*)d_in[4];   // [128, 512]
    const float* lags  = (const float*)d_in[5];   // [256]
    const float* gates = (const float*)d_in[6];   // [256]
    const void*  ml    = (n_in > 7) ? d_in[7] : nullptr;

    prep_kernel<<<NB, 512>>>(query, Wq, Wk, lags, gates, ml);
    main_kernel<<<dim3(CPB, NB), 128>>>(embs);
    finish_kernel<<<16, 512>>>(Wv, (float*)d_out);
}